// round 13
// baseline (speedup 1.0000x reference)
#include <cuda_runtime.h>
#include <cuda_fp16.h>
#include <stdint.h>

#define IN_F   4096
#define OUT_F  11008
#define BATCH  16

#define K_TASK   512                    // k per task
#define NTILES   1376                   // n-tiles of 8 channels
#define NKC      8                      // k-chunks
#define NTASKS   (NTILES * NKC)         // 11008, kc-major: tau = kc*1376 + n

#define BLOCKS   148
#define NCONS    5                      // consumer warps
#define THREADS  ((NCONS + 1) * 32)     // 192: 5 consumers + 1 producer
#define RING     (2 * NCONS)            // 10 slots; warp w owns {w, w+5}

#define WROW_B   2112                   // 2048 + 64 pad -> conflict-free LDS.128
#define SLOT_B   (8 * WROW_B)           // 16,896 B per slot
#define SLOT_TX  16384                  // 8 x 2048 actual bytes per fill
#define XROW_H   520                    // halves per x row (512 + 8 pad)
#define XSLICE_B (BATCH * XROW_H * 2)   // 16,640 B per x slice

#define SMEM_MBAR 0                     // slot s: full @ s*16, empty @ s*16+8
#define SMEM_X    256                   // two slices: kc_lo @ 0, kc_hi @ XSLICE_B
#define SMEM_W    (SMEM_X + 2 * XSLICE_B)          // 256 + 33280 = 33,536
#define SMEM_TOT  (SMEM_W + RING * SLOT_B)         // 202,496 B

// ---------------- mbarrier helpers ----------------
#define MB_INIT(addr, cnt) \
    asm volatile("mbarrier.init.shared.b64 [%0], %1;" :: "r"(addr), "r"(cnt) : "memory")
#define MB_EXPECT_TX(addr, bytes) \
    asm volatile("mbarrier.arrive.expect_tx.shared.b64 _, [%0], %1;" :: "r"(addr), "r"(bytes) : "memory")
#define MB_ARRIVE(addr) \
    asm volatile("mbarrier.arrive.shared.b64 _, [%0];" :: "r"(addr) : "memory")
#define MB_WAIT(addr, parity) do {                                            \
    unsigned _done;                                                           \
    asm volatile("{\n\t.reg .pred p;\n\t"                                     \
        "mbarrier.try_wait.parity.acquire.cta.shared::cta.b64 p, [%1], %2;\n\t" \
        "selp.b32 %0, 1, 0, p;\n\t}"                                          \
        : "=r"(_done) : "r"(addr), "r"(parity) : "memory");                   \
    while (!_done) {                                                          \
        asm volatile("{\n\t.reg .pred p;\n\t"                                 \
            "mbarrier.try_wait.parity.acquire.cta.shared::cta.b64 p, [%1], %2, 0x989680;\n\t" \
            "selp.b32 %0, 1, 0, p;\n\t}"                                      \
            : "=r"(_done) : "r"(addr), "r"(parity) : "memory");               \
    }                                                                         \
} while (0)

#define BULK_CP(dst, src, mbar) \
    asm volatile("cp.async.bulk.shared::cta.global.mbarrier::complete_tx::bytes " \
                 "[%0], [%1], %2, [%3];" \
                 :: "r"(dst), "l"(src), "n"(2048), "r"(mbar) : "memory")

// ---------------------------------------------------------------------------
// Prologue: out = bias (broadcast). (x conversion now done in-block.)
// ---------------------------------------------------------------------------
__global__ void prologue_kernel(const float* __restrict__ bias,
                                float* __restrict__ out) {
    const int i      = blockIdx.x * blockDim.x + threadIdx.x;
    const int stride = gridDim.x * blockDim.x;
    const float4* b4 = (const float4*)bias;
    const int total4 = BATCH * OUT_F / 4;
    const int row4   = OUT_F / 4;
    for (int j = i; j < total4; j += stride) {
        ((float4*)out)[j] = __ldg(b4 + (j % row4));
    }
}

// ---------------------------------------------------------------------------
// GEMM: block b owns contiguous tasks [b*NTASKS/148, (b+1)*NTASKS/148) over
// kc-major ids (74-75 tasks, perfectly balanced; range spans <= 2 k-chunks,
// both x slices staged). Producer streams 16KB weight tasks into a 10-slot
// ring (8 lanes issue 2KB bulk copies); consumer warp w owns slots {w, w+5}.
// x is converted fp32->fp16 (k-permuted) directly from gmem into smem; the
// permutation makes a raw 16B weight quad equal the MMA B fragment.
// ---------------------------------------------------------------------------
extern __shared__ char smem[];

__global__ void __launch_bounds__(THREADS, 1)
gemm_kernel(const float* __restrict__ X,
            const int*   __restrict__ W,
            const float* __restrict__ scale,
            float*       __restrict__ out) {
    const int tid  = threadIdx.x;
    const int lane = tid & 31;
    const int wid  = tid >> 5;

    const int start = (int)(((long long)blockIdx.x     * NTASKS) / BLOCKS);
    const int end   = (int)(((long long)(blockIdx.x+1) * NTASKS) / BLOCKS);
    const int T     = end - start;
    const int kc_lo = start / NTILES;
    const int kc_hi = (end - 1) / NTILES;

    const unsigned sb = (unsigned)__cvta_generic_to_shared(smem);

    // ---- init mbarriers ----
    if (tid == 0) {
        #pragma unroll
        for (int s = 0; s < RING; s++) {
            MB_INIT(sb + SMEM_MBAR + s * 16,     1u);   // full
            MB_INIT(sb + SMEM_MBAR + s * 16 + 8, 1u);   // empty
        }
        asm volatile("fence.proxy.async.shared::cta;" ::: "memory");
    }

    // ---- stage x slices (fp32 gmem -> fp16 smem, k-permuted) ----
    {
        const int kcs[2] = { kc_lo, kc_hi };
        #pragma unroll
        for (int s = 0; s < 2; s++) {
            const float2* src = (const float2*)X;
            char* dstbase = smem + SMEM_X + s * XSLICE_B;
            // 16 rows x 256 half2-pairs
            for (int i = tid; i < BATCH * 256; i += THREADS) {
                const int r = i >> 8, p = i & 255;
                float2 v = __ldg(src + r * (IN_F / 2) + kcs[s] * 256 + p);
                const int q  = p & 7;
                const int pp = (p & ~7) | ((q & 1) << 2) | (q >> 1);
                *(__half2*)(dstbase + r * (XROW_H * 2) + pp * 4) =
                    __floats2half2_rn(v.x, v.y);
            }
        }
    }
    __syncthreads();

    if (wid == NCONS) {
        // ================= producer =================
        for (int j = 0; j < T; j++) {
            const int slot = j % RING;
            const int lap  = j / RING;
            const unsigned full_bar = sb + SMEM_MBAR + slot * 16;
            if (lane == 0) {
                MB_WAIT(full_bar + 8, (unsigned)((lap & 1) ^ 1));
                MB_EXPECT_TX(full_bar, (unsigned)SLOT_TX);
            }
            __syncwarp();
            const int tau = start + j;
            const int kc  = tau / NTILES;
            const int n   = tau - kc * NTILES;
            if (lane < 8) {
                const char* src = (const char*)(W + (size_t)(n * 8 + lane) * IN_F
                                                  + kc * K_TASK);
                BULK_CP(sb + SMEM_W + slot * SLOT_B + lane * WROW_B, src, full_bar);
            }
        }
        return;
    }

    // ================= consumers (warps 0..4) =================
    const int ng = lane >> 2;      // weight row within n-tile
    const int tq = lane & 3;       // k-quad

    const unsigned x_off = sb + SMEM_X +
        (unsigned)((lane & 15) * (XROW_H * 2) + ((lane >> 4) & 1) * 16);
    const char* wbase = smem + SMEM_W + ng * WROW_B + tq * 16;
    const unsigned mb = sb + SMEM_MBAR;

    // warp w: r-th task j = w + 5r, slot w + 5*(r&1), fill #(r>>1)
    int r = 0;
    for (int j = wid; j < T; j += NCONS, r++) {
        const int      slot = wid + NCONS * (r & 1);
        const unsigned par  = (unsigned)((r >> 1) & 1);
        MB_WAIT(mb + slot * 16, par);

        const int tau = start + j;
        const int kc  = tau / NTILES;
        const int n   = tau - kc * NTILES;
        const unsigned a_off = x_off + (unsigned)((kc != kc_lo) ? XSLICE_B : 0);

        const char* wslot = wbase + slot * SLOT_B;
        float c0 = 0.f, c1 = 0.f, c2 = 0.f, c3 = 0.f;

        #pragma unroll 1
        for (int g = 0; g < 4; g++) {            // 4 groups of 8 k16-tiles
            #pragma unroll
            for (int i = 0; i < 8; i++) {
                const int t = g * 8 + i;
                unsigned a0, a1, a2, a3;
                asm volatile(
                    "ldmatrix.sync.aligned.m8n8.x4.shared.b16 {%0,%1,%2,%3}, [%4];"
                    : "=r"(a0), "=r"(a1), "=r"(a2), "=r"(a3)
                    : "r"(a_off + (unsigned)(t * 32)));

                int4 w = *(const int4*)(wslot + t * 64);
                __half2 hb0 = __halves2half2(__int2half_rn(w.x), __int2half_rn(w.y));
                __half2 hb1 = __halves2half2(__int2half_rn(w.z), __int2half_rn(w.w));
                unsigned b0 = *reinterpret_cast<unsigned*>(&hb0);
                unsigned b1 = *reinterpret_cast<unsigned*>(&hb1);

                asm volatile(
                    "mma.sync.aligned.m16n8k16.row.col.f32.f16.f16.f32 "
                    "{%0,%1,%2,%3}, {%4,%5,%6,%7}, {%8,%9}, {%0,%1,%2,%3};"
                    : "+f"(c0), "+f"(c1), "+f"(c2), "+f"(c3)
                    : "r"(a0), "r"(a1), "r"(a2), "r"(a3), "r"(b0), "r"(b1));
            }
        }

        __syncwarp();
        if (lane == 0) MB_ARRIVE(mb + slot * 16 + 8);

        // ---- epilogue: scale, accumulate (out already holds bias) ----
        const int o0 = n * 8 + tq * 2;
        const float s0  = __ldg(scale + o0);
        const float s1f = __ldg(scale + o0 + 1);
        atomicAdd(&out[(size_t)ng * OUT_F + o0],           c0 * s0);
        atomicAdd(&out[(size_t)ng * OUT_F + o0 + 1],       c1 * s1f);
        atomicAdd(&out[(size_t)(ng + 8) * OUT_F + o0],     c2 * s0);
        atomicAdd(&out[(size_t)(ng + 8) * OUT_F + o0 + 1], c3 * s1f);
    }
}

// ---------------------------------------------------------------------------
extern "C" void kernel_launch(void* const* d_in, const int* in_sizes, int n_in,
                              void* d_out, int out_size) {
    const float* x     = (const float*)d_in[0];
    const int*   w     = (const int*)  d_in[1];
    const float* scale = (const float*)d_in[2];
    const float* bias  = (const float*)d_in[3];
    float*       out   = (float*)d_out;

    cudaFuncSetAttribute(gemm_kernel,
                         cudaFuncAttributeMaxDynamicSharedMemorySize, SMEM_TOT);

    prologue_kernel<<<148, 256>>>(bias, out);
    gemm_kernel<<<BLOCKS, THREADS, SMEM_TOT>>>(x, w, scale, out);
}

// round 15
// speedup vs baseline: 1.0361x; 1.0361x over previous
#include <cuda_runtime.h>
#include <cuda_fp16.h>
#include <stdint.h>

#define IN_F   4096
#define OUT_F  11008
#define BATCH  16

#define K_TASK   512                    // k per task (per-block k-chunk)
#define NTILES   1376                   // n-tiles of 8 channels

#define BLOCKS   148
#define THREADS  256                    // 6 consumers + 2 producer warps
#define NCONS    6
#define RING     12                     // warp w owns slots {w, w+6}

#define WROW_B   2112                   // 2048 + 64 pad -> conflict-free LDS.128
#define SLOT_B   (8 * WROW_B)           // 16,896 B per slot
#define SLOT_TX  16384                  // 8 x 2048 actual bytes per fill
#define XROW_H   520                    // halves per x row (512 + 8 pad)

#define SMEM_MBAR 0                     // slot s: full @ s*16, empty @ s*16+8
#define SMEM_X    256
#define SMEM_W    (SMEM_X + BATCH * XROW_H * 2)   // 256 + 16640 = 16896
#define SMEM_TOT  (SMEM_W + RING * SLOT_B)        // 219,648 B (< 227KB opt-in)

// ---------------- mbarrier helpers ----------------
#define MB_INIT(addr, cnt) \
    asm volatile("mbarrier.init.shared.b64 [%0], %1;" :: "r"(addr), "r"(cnt) : "memory")
#define MB_EXPECT_TX(addr, bytes) \
    asm volatile("mbarrier.arrive.expect_tx.shared.b64 _, [%0], %1;" :: "r"(addr), "r"(bytes) : "memory")
#define MB_ARRIVE(addr) \
    asm volatile("mbarrier.arrive.shared.b64 _, [%0];" :: "r"(addr) : "memory")
#define MB_WAIT(addr, parity) do {                                            \
    unsigned _done;                                                           \
    asm volatile("{\n\t.reg .pred p;\n\t"                                     \
        "mbarrier.try_wait.parity.acquire.cta.shared::cta.b64 p, [%1], %2;\n\t" \
        "selp.b32 %0, 1, 0, p;\n\t}"                                          \
        : "=r"(_done) : "r"(addr), "r"(parity) : "memory");                   \
    while (!_done) {                                                          \
        asm volatile("{\n\t.reg .pred p;\n\t"                                 \
            "mbarrier.try_wait.parity.acquire.cta.shared::cta.b64 p, [%1], %2, 0x989680;\n\t" \
            "selp.b32 %0, 1, 0, p;\n\t}"                                      \
            : "=r"(_done) : "r"(addr), "r"(parity) : "memory");               \
    }                                                                         \
} while (0)

#define BULK_CP(dst, src, mbar) \
    asm volatile("cp.async.bulk.shared::cta.global.mbarrier::complete_tx::bytes " \
                 "[%0], [%1], %2, [%3];" \
                 :: "r"(dst), "l"(src), "n"(2048), "r"(mbar) : "memory")

// ---------------------------------------------------------------------------
// Prologue: out = bias (broadcast) only.
// ---------------------------------------------------------------------------
__global__ void prologue_kernel(const float* __restrict__ bias,
                                float* __restrict__ out) {
    const int i      = blockIdx.x * blockDim.x + threadIdx.x;
    const int stride = gridDim.x * blockDim.x;
    const float4* b4 = (const float4*)bias;
    const int total4 = BATCH * OUT_F / 4;
    const int row4   = OUT_F / 4;
    for (int j = i; j < total4; j += stride) {
        ((float4*)out)[j] = __ldg(b4 + (j % row4));
    }
}

// ---------------------------------------------------------------------------
// GEMM: per-block k-chunk (kc = blockIdx&7); TWO producer warps with
// independent cursors (A: slots 0-5, B: slots 6-11; task j -> producer
// (j/6)&1) stream 16KB weight tasks into a 12-slot ring; consumer warp w
// exclusively owns slots {w, w+6} (task j -> warp j%6, slot j%12).
// x is converted fp32->fp16 (k-permuted) from gmem in-block; the permutation
// makes a raw 16B weight quad equal the MMA B fragment.
// ---------------------------------------------------------------------------
extern __shared__ char smem[];

__global__ void __launch_bounds__(THREADS, 1)
gemm_kernel(const float* __restrict__ X,
            const int*   __restrict__ W,
            const float* __restrict__ scale,
            float*       __restrict__ out) {
    const int tid  = threadIdx.x;
    const int lane = tid & 31;
    const int wid  = tid >> 5;

    const int kc  = blockIdx.x & 7;
    const int bi  = blockIdx.x >> 3;
    const int Bkc = (kc < 4) ? 19 : 18;             // blocks sharing this kc
    const int T   = (NTILES - bi + Bkc - 1) / Bkc;  // tasks for this block

    const unsigned sb = (unsigned)__cvta_generic_to_shared(smem);

    // ---- init mbarriers ----
    if (tid == 0) {
        #pragma unroll
        for (int s = 0; s < RING; s++) {
            MB_INIT(sb + SMEM_MBAR + s * 16,     1u);   // full
            MB_INIT(sb + SMEM_MBAR + s * 16 + 8, 1u);   // empty
        }
        asm volatile("fence.proxy.async.shared::cta;" ::: "memory");
    }

    // ---- stage this block's x k-slice (fp32 gmem -> fp16 smem, permuted) ----
    {
        const float2* src = (const float2*)X;
        // 16 rows x 256 half2-pairs
        for (int i = tid; i < BATCH * 256; i += THREADS) {
            const int r = i >> 8, p = i & 255;
            float2 v = __ldg(src + r * (IN_F / 2) + kc * 256 + p);
            const int q  = p & 7;
            const int pp = (p & ~7) | ((q & 1) << 2) | (q >> 1);
            *(__half2*)(smem + SMEM_X + r * (XROW_H * 2) + pp * 4) =
                __floats2half2_rn(v.x, v.y);
        }
    }
    __syncthreads();

    if (wid >= NCONS) {
        // ================= producers (warps 6,7) =================
        const int p = wid - NCONS;      // 0 -> slots 0-5, 1 -> slots 6-11
        if (lane == 0) {
            for (int j = 0; j < T; j++) {
                if (((j / 6) & 1) != p) continue;
                const int slot = j % RING;
                const int lap  = j / RING;
                MB_WAIT(sb + SMEM_MBAR + slot * 16 + 8, (unsigned)((lap & 1) ^ 1));
                MB_EXPECT_TX(sb + SMEM_MBAR + slot * 16, (unsigned)SLOT_TX);

                const int n = bi + j * Bkc;
                const char* src = (const char*)(W + (size_t)n * 8 * IN_F + kc * K_TASK);
                const unsigned dst = sb + SMEM_W + slot * SLOT_B;
                #pragma unroll
                for (int r = 0; r < 8; r++) {
                    BULK_CP(dst + r * WROW_B, src + (size_t)r * (IN_F * 4),
                            sb + SMEM_MBAR + slot * 16);
                }
            }
        }
        return;
    }

    // ================= consumers (warps 0..5) =================
    const int ng = lane >> 2;      // weight row within n-tile
    const int tq = lane & 3;       // k-quad

    const unsigned a_off = sb + SMEM_X +
        (unsigned)((lane & 15) * (XROW_H * 2) + ((lane >> 4) & 1) * 16);
    const char* wbase = smem + SMEM_W + ng * WROW_B + tq * 16;
    const unsigned mb = sb + SMEM_MBAR;

    // warp w: r-th task is j = w + 6r, in slot w + 6*(r&1), fill #(r>>1)
    int r = 0;
    for (int j = wid; j < T; j += NCONS, r++) {
        const int      slot = wid + NCONS * (r & 1);
        const unsigned par  = (unsigned)((r >> 1) & 1);
        MB_WAIT(mb + slot * 16, par);

        const int n = bi + j * Bkc;
        const char* wslot = wbase + slot * SLOT_B;
        float c0 = 0.f, c1 = 0.f, c2 = 0.f, c3 = 0.f;

        #pragma unroll 1
        for (int g = 0; g < 4; g++) {            // 4 groups of 8 k16-tiles
            #pragma unroll
            for (int i = 0; i < 8; i++) {
                const int t = g * 8 + i;
                unsigned a0, a1, a2, a3;
                asm volatile(
                    "ldmatrix.sync.aligned.m8n8.x4.shared.b16 {%0,%1,%2,%3}, [%4];"
                    : "=r"(a0), "=r"(a1), "=r"(a2), "=r"(a3)
                    : "r"(a_off + (unsigned)(t * 32)));

                int4 w = *(const int4*)(wslot + t * 64);
                __half2 hb0 = __halves2half2(__int2half_rn(w.x), __int2half_rn(w.y));
                __half2 hb1 = __halves2half2(__int2half_rn(w.z), __int2half_rn(w.w));
                unsigned b0 = *reinterpret_cast<unsigned*>(&hb0);
                unsigned b1 = *reinterpret_cast<unsigned*>(&hb1);

                asm volatile(
                    "mma.sync.aligned.m16n8k16.row.col.f32.f16.f16.f32 "
                    "{%0,%1,%2,%3}, {%4,%5,%6,%7}, {%8,%9}, {%0,%1,%2,%3};"
                    : "+f"(c0), "+f"(c1), "+f"(c2), "+f"(c3)
                    : "r"(a0), "r"(a1), "r"(a2), "r"(a3), "r"(b0), "r"(b1));
            }
        }

        __syncwarp();
        if (lane == 0) MB_ARRIVE(mb + slot * 16 + 8);

        // ---- epilogue: scale, accumulate (out already holds bias) ----
        const int o0 = n * 8 + tq * 2;
        const float s0  = __ldg(scale + o0);
        const float s1f = __ldg(scale + o0 + 1);
        atomicAdd(&out[(size_t)ng * OUT_F + o0],           c0 * s0);
        atomicAdd(&out[(size_t)ng * OUT_F + o0 + 1],       c1 * s1f);
        atomicAdd(&out[(size_t)(ng + 8) * OUT_F + o0],     c2 * s0);
        atomicAdd(&out[(size_t)(ng + 8) * OUT_F + o0 + 1], c3 * s1f);
    }
}

// ---------------------------------------------------------------------------
extern "C" void kernel_launch(void* const* d_in, const int* in_sizes, int n_in,
                              void* d_out, int out_size) {
    const float* x     = (const float*)d_in[0];
    const int*   w     = (const int*)  d_in[1];
    const float* scale = (const float*)d_in[2];
    const float* bias  = (const float*)d_in[3];
    float*       out   = (float*)d_out;

    cudaFuncSetAttribute(gemm_kernel,
                         cudaFuncAttributeMaxDynamicSharedMemorySize, SMEM_TOT);

    prologue_kernel<<<148, 256>>>(bias, out);
    gemm_kernel<<<BLOCKS, THREADS, SMEM_TOT>>>(x, w, scale, out);
}